// round 7
// baseline (speedup 1.0000x reference)
#include <cuda_runtime.h>
#include <math.h>
#include <float.h>

#define NOBJ   16
#define P      4096
#define EPSF   1e-12f
#define GRID   96
#define NBINS  (GRID * GRID)          // 9216
#define NCHUNKS (NBINS / 256)         // 36
#define GMIN   (-5.0f)
#define GEXT   10.0f
#define CELLF  (GEXT / (float)GRID)   // ~0.10417
#define INVC   ((float)GRID / GEXT)   // 9.6
#define NSLOT  32                     // 2 sets x 16 objects

// Sorted points and cell offsets per (set, object) slot.
__device__ float2       g_pts[NSLOT * P];
__device__ unsigned int g_cstart[NSLOT * (NBINS + 1)];
__device__ float        g_mask[NOBJ];

__device__ __forceinline__ int cell_of(float v) {
    int c = (int)((v - GMIN) * INVC);
    return min(GRID - 1, max(0, c));
}

// ---------------------------------------------------------------------------
// Kernel 1: build — counting-sort each (set, obj) into the 96x96 grid.
// One CTA per slot. Slot s: set = s>>4, obj = s&15. Also computes g_mask
// for set2 slots and zeroes the output scalar.
// ---------------------------------------------------------------------------
__global__ void __launch_bounds__(256)
build_kernel(const float* __restrict__ set1, const float* __restrict__ set2,
             float* __restrict__ out)
{
    const int slot = blockIdx.x;
    const int set  = slot >> 4;
    const int obj  = slot & 15;
    const float2* pts = (const float2*)((set == 0 ? set1 : set2) + (size_t)obj * P * 2);

    __shared__ unsigned int hist[NBINS];     // 36 KB
    __shared__ unsigned int wsum[8];
    __shared__ unsigned int s_carry, s_total;

    const int tid = threadIdx.x;
    const int lane = tid & 31, warp = tid >> 5;

    for (int i = tid; i < NBINS; i += 256) hist[i] = 0;
    if (tid == 0) { s_carry = 0; }
    __syncthreads();

    // histogram pass (+ mask sum for set2)
    float msum = 0.f;
    for (int i = tid; i < P; i += 256) {
        float2 p = pts[i];
        msum += p.x + p.y;
        int c = cell_of(p.y) * GRID + cell_of(p.x);
        atomicAdd(&hist[c], 1u);
    }

    if (set == 1) {
        #pragma unroll
        for (int o = 16; o; o >>= 1) msum += __shfl_xor_sync(0xFFFFFFFFu, msum, o);
        __shared__ float mred[8];
        if (lane == 0) mred[warp] = msum;
        __syncthreads();
        if (tid == 0) {
            float t = 0.f;
            #pragma unroll
            for (int w = 0; w < 8; w++) t += mred[w];
            g_mask[obj] = (t >= 0.f) ? 1.f : 0.f;
        }
    }
    if (slot == 0 && tid == 0) *out = 0.f;
    __syncthreads();

    // exclusive scan over NBINS (36 chunks of 256)
    for (int ch = 0; ch < NCHUNKS; ch++) {
        unsigned int v = hist[ch * 256 + tid];
        unsigned int incl = v;
        #pragma unroll
        for (int o = 1; o < 32; o <<= 1) {
            unsigned int n = __shfl_up_sync(0xFFFFFFFFu, incl, o);
            if (lane >= o) incl += n;
        }
        if (lane == 31) wsum[warp] = incl;
        __syncthreads();
        if (tid == 0) {
            unsigned int run = 0;
            #pragma unroll
            for (int w = 0; w < 8; w++) { unsigned int t = wsum[w]; wsum[w] = run; run += t; }
            s_total = run;
        }
        __syncthreads();
        hist[ch * 256 + tid] = (incl - v) + wsum[warp] + s_carry;
        __syncthreads();
        if (tid == 0) s_carry += s_total;
        __syncthreads();
    }

    // persist starts
    unsigned int* cs = g_cstart + (size_t)slot * (NBINS + 1);
    for (int i = tid; i < NBINS; i += 256) cs[i] = hist[i];
    if (tid == 0) cs[NBINS] = P;
    __syncthreads();

    // scatter (hist becomes per-cell cursor)
    float2* dst = g_pts + (size_t)slot * P;
    for (int i = tid; i < P; i += 256) {
        float2 p = pts[i];
        int c = cell_of(p.y) * GRID + cell_of(p.x);
        unsigned int pos = atomicAdd(&hist[c], 1u);
        dst[pos] = p;
    }
}

// ---------------------------------------------------------------------------
// Kernel 2: query — ring NN search. Queries are read in SORTED order (from
// g_pts of the query slot) so warps are spatially coherent. Sum is order-
// invariant, so this is exact.
// ---------------------------------------------------------------------------
__global__ void __launch_bounds__(256)
query_kernel(float* __restrict__ out)
{
    const int q    = blockIdx.x * 256 + threadIdx.x;   // [0, 131072)
    const int dir  = q >> 16;
    const int obj  = (q >> 12) & 15;
    const int qi   = q & (P - 1);

    const int qslot = (dir == 0) ? obj        : 16 + obj;
    const int tslot = (dir == 0) ? 16 + obj   : obj;

    const float2 qp = g_pts[(size_t)qslot * P + qi];
    const float qx = qp.x, qy = qp.y;
    const unsigned int* __restrict__ cs = g_cstart + (size_t)tslot * (NBINS + 1);
    const float2* __restrict__ tp = g_pts + (size_t)tslot * P;

    const int cx = cell_of(qx), cy = cell_of(qy);

    float best = FLT_MAX;

    for (int r = 0; r < GRID; r++) {
        float lb = (float)(r - 1) * CELLF;
        if (lb < 0.f) lb = 0.f;
        if (best <= lb * lb) break;

        const int x0 = cx - r, x1 = cx + r;
        const int y0 = cy - r, y1 = cy + r;

        for (int j = y0; j <= y1; j++) {
            if (j < 0 || j > GRID - 1) continue;
            const bool interior = (j > y0) && (j < y1);
            // cells to visit in this row
            int ia = max(x0, 0), ib = min(x1, GRID - 1);
            for (int i = ia; i <= ib; i++) {
                if (interior && i != x0 && i != x1) { i = x1 - 1; continue; }
                const int c = j * GRID + i;
                const unsigned int k0 = cs[c], k1 = cs[c + 1];
                if (k0 == k1) continue;
                // exact cell-box lower bound
                const float bx0 = GMIN + (float)i * CELLF;
                const float by0 = GMIN + (float)j * CELLF;
                const float ddx = fmaxf(fmaxf(bx0 - qx, qx - (bx0 + CELLF)), 0.f);
                const float ddy = fmaxf(fmaxf(by0 - qy, qy - (by0 + CELLF)), 0.f);
                if (fmaf(ddx, ddx, ddy * ddy) >= best) continue;
                for (unsigned int k = k0; k < k1; k++) {
                    const float2 p = tp[k];
                    const float dx = qx - p.x;
                    const float dy = qy - p.y;
                    const float d2 = fmaf(dx, dx, dy * dy);
                    best = fminf(best, d2);
                }
            }
        }
    }

    float acc = sqrtf(fmaxf(best, EPSF)) * g_mask[obj];

    // block reduce + atomic
    #pragma unroll
    for (int o = 16; o; o >>= 1) acc += __shfl_xor_sync(0xFFFFFFFFu, acc, o);
    __shared__ float red[8];
    if ((threadIdx.x & 31) == 0) red[threadIdx.x >> 5] = acc;
    __syncthreads();
    if (threadIdx.x == 0) {
        float tot = 0.f;
        #pragma unroll
        for (int w = 0; w < 8; w++) tot += red[w];
        atomicAdd(out, tot * (0.5f / ((float)NOBJ * (float)P)));
    }
}

// ---------------------------------------------------------------------------
extern "C" void kernel_launch(void* const* d_in, const int* in_sizes, int n_in,
                              void* d_out, int out_size)
{
    const float* set1 = (const float*)d_in[0];
    const float* set2 = (const float*)d_in[1];
    float* out = (float*)d_out;

    build_kernel<<<NSLOT, 256>>>(set1, set2, out);
    query_kernel<<<(2 * NOBJ * P) / 256, 256>>>(out);
}

// round 10
// speedup vs baseline: 2.4971x; 2.4971x over previous
#include <cuda_runtime.h>
#include <math.h>
#include <float.h>

#define NOBJ   16
#define P      4096
#define EPSF   1e-12f
#define GRID   64
#define NBINS  (GRID * GRID)          // 4096
#define NCHUNKS (NBINS / 256)         // 16
#define GMIN   (-5.0f)
#define GEXT   10.0f
#define CELLF  (GEXT / (float)GRID)   // 0.15625
#define INVC   ((float)GRID / GEXT)   // 6.4
#define NSLOT  32                     // 2 sets x 16 objects
#define CSTRIDE (NBINS + 4)           // u32 stride per slot: 4100*4 = 16400 B (16B-aligned)

// Sorted points and cell offsets per (set, object) slot.
__device__ __align__(16) float2       g_pts[NSLOT * P];
__device__ __align__(16) unsigned int g_cstart[NSLOT * CSTRIDE];
__device__ float        g_mask[NOBJ];

__device__ __forceinline__ int cell_of(float v) {
    int c = (int)((v - GMIN) * INVC);
    return min(GRID - 1, max(0, c));
}

// ---------------------------------------------------------------------------
// Kernel 1: build — counting-sort each (set, obj) into the 64x64 grid.
// One CTA per slot. Also computes g_mask (set2) and zeroes the output.
// Clamped outliers are safe: lower bounds only under-estimate distances to
// clamped points, so pruning stays exact.
// ---------------------------------------------------------------------------
__global__ void __launch_bounds__(256)
build_kernel(const float* __restrict__ set1, const float* __restrict__ set2,
             float* __restrict__ out)
{
    const int slot = blockIdx.x;
    const int set  = slot >> 4;
    const int obj  = slot & 15;
    const float2* pts = (const float2*)((set == 0 ? set1 : set2) + (size_t)obj * P * 2);

    __shared__ unsigned int hist[NBINS];     // 16 KB
    __shared__ unsigned int wsum[8];
    __shared__ unsigned int s_carry, s_total;

    const int tid = threadIdx.x;
    const int lane = tid & 31, warp = tid >> 5;

    for (int i = tid; i < NBINS; i += 256) hist[i] = 0;
    if (tid == 0) s_carry = 0;
    __syncthreads();

    // histogram pass (+ mask sum for set2)
    float msum = 0.f;
    for (int i = tid; i < P; i += 256) {
        float2 p = pts[i];
        msum += p.x + p.y;
        int c = cell_of(p.y) * GRID + cell_of(p.x);
        atomicAdd(&hist[c], 1u);
    }

    if (set == 1) {
        #pragma unroll
        for (int o = 16; o; o >>= 1) msum += __shfl_xor_sync(0xFFFFFFFFu, msum, o);
        __shared__ float mred[8];
        if (lane == 0) mred[warp] = msum;
        __syncthreads();
        if (tid == 0) {
            float t = 0.f;
            #pragma unroll
            for (int w = 0; w < 8; w++) t += mred[w];
            g_mask[obj] = (t >= 0.f) ? 1.f : 0.f;
        }
    }
    if (slot == 0 && tid == 0) *out = 0.f;
    __syncthreads();

    // exclusive scan over NBINS (16 chunks of 256)
    for (int ch = 0; ch < NCHUNKS; ch++) {
        unsigned int v = hist[ch * 256 + tid];
        unsigned int incl = v;
        #pragma unroll
        for (int o = 1; o < 32; o <<= 1) {
            unsigned int n = __shfl_up_sync(0xFFFFFFFFu, incl, o);
            if (lane >= o) incl += n;
        }
        if (lane == 31) wsum[warp] = incl;
        __syncthreads();
        if (tid == 0) {
            unsigned int run = 0;
            #pragma unroll
            for (int w = 0; w < 8; w++) { unsigned int t = wsum[w]; wsum[w] = run; run += t; }
            s_total = run;
        }
        __syncthreads();
        hist[ch * 256 + tid] = (incl - v) + wsum[warp] + s_carry;
        __syncthreads();
        if (tid == 0) s_carry += s_total;
        __syncthreads();
    }

    // persist starts (stride CSTRIDE keeps every slot 16B-aligned)
    unsigned int* cs = g_cstart + (size_t)slot * CSTRIDE;
    for (int i = tid; i < NBINS; i += 256) cs[i] = hist[i];
    if (tid == 0) { cs[NBINS] = P; cs[NBINS + 1] = P; cs[NBINS + 2] = P; cs[NBINS + 3] = P; }
    __syncthreads();

    // scatter (hist becomes per-cell cursor)
    float2* dst = g_pts + (size_t)slot * P;
    for (int i = tid; i < P; i += 256) {
        float2 p = pts[i];
        int c = cell_of(p.y) * GRID + cell_of(p.x);
        unsigned int pos = atomicAdd(&hist[c], 1u);
        dst[pos] = p;
    }
}

// ---------------------------------------------------------------------------
// Kernel 2: query — ring NN search with the ENTIRE target structure staged
// in shared memory (points 32 KB + cell starts 16 KB). Queries read in
// sorted order -> warp-coherent walks -> broadcast LDS.
// blockIdx.x = dir(2) | obj(16) | chunk(16) -> 512 CTAs, 1 query/thread.
// ---------------------------------------------------------------------------
__global__ void __launch_bounds__(256)
query_kernel(float* __restrict__ out)
{
    const int b     = blockIdx.x;
    const int chunk = b & 15;            // 16 chunks of 256 queries
    const int obj   = (b >> 4) & 15;
    const int dir   = b >> 8;

    const int qslot = (dir == 0) ? obj      : 16 + obj;
    const int tslot = (dir == 0) ? 16 + obj : obj;

    __shared__ __align__(16) float2       s_pts[P];           // 32 KB
    __shared__ __align__(16) unsigned int s_cs[NBINS + 1];    // 16 KB

    // stage target structure (float4 / uint4 copies; sources 16B-aligned)
    {
        const float4* src = (const float4*)(g_pts + (size_t)tslot * P);
        float4* dst = (float4*)s_pts;
        for (int i = threadIdx.x; i < P / 2; i += 256) dst[i] = src[i];
        const uint4* csrc = (const uint4*)(g_cstart + (size_t)tslot * CSTRIDE);
        uint4* cdst = (uint4*)s_cs;
        for (int i = threadIdx.x; i < NBINS / 4; i += 256) cdst[i] = csrc[i];
        if (threadIdx.x == 0) s_cs[NBINS] = P;
    }
    __syncthreads();

    const int qi = chunk * 256 + threadIdx.x;
    const float2 qp = g_pts[(size_t)qslot * P + qi];
    const float qx = qp.x, qy = qp.y;
    const int cx = cell_of(qx), cy = cell_of(qy);

    float best = FLT_MAX;

    // fast path: 3x3 block (rings 0 and 1), contiguous row spans
    {
        const int j0 = max(cy - 1, 0), j1 = min(cy + 1, GRID - 1);
        const int i0 = max(cx - 1, 0), i1 = min(cx + 1, GRID - 1);
        for (int j = j0; j <= j1; j++) {
            const unsigned int k0 = s_cs[j * GRID + i0];
            const unsigned int k1 = s_cs[j * GRID + i1 + 1];
            for (unsigned int k = k0; k < k1; k++) {
                const float2 p = s_pts[k];
                const float dx = qx - p.x;
                const float dy = qy - p.y;
                best = fminf(best, fmaf(dx, dx, dy * dy));
            }
        }
    }

    // generic expanding rings from r = 2
    for (int r = 2; r < GRID; r++) {
        const float lb = (float)(r - 1) * CELLF;
        if (best <= lb * lb) break;

        const int x0 = cx - r, x1 = cx + r;
        const int y0 = cy - r, y1 = cy + r;

        for (int j = max(y0, 0); j <= min(y1, GRID - 1); j++) {
            const bool interior = (j > y0) && (j < y1);
            const int ia = max(x0, 0), ib = min(x1, GRID - 1);
            for (int i = ia; i <= ib; i++) {
                if (interior && i != x0 && i != x1) { i = x1 - 1; continue; }
                const int c = j * GRID + i;
                const unsigned int k0 = s_cs[c], k1 = s_cs[c + 1];
                if (k0 == k1) continue;
                // exact cell-box lower bound
                const float bx0 = GMIN + (float)i * CELLF;
                const float by0 = GMIN + (float)j * CELLF;
                const float ddx = fmaxf(fmaxf(bx0 - qx, qx - (bx0 + CELLF)), 0.f);
                const float ddy = fmaxf(fmaxf(by0 - qy, qy - (by0 + CELLF)), 0.f);
                if (fmaf(ddx, ddx, ddy * ddy) >= best) continue;
                for (unsigned int k = k0; k < k1; k++) {
                    const float2 p = s_pts[k];
                    const float dx = qx - p.x;
                    const float dy = qy - p.y;
                    best = fminf(best, fmaf(dx, dx, dy * dy));
                }
            }
        }
    }

    float acc = sqrtf(fmaxf(best, EPSF)) * g_mask[obj];

    // block reduce + atomic
    #pragma unroll
    for (int o = 16; o; o >>= 1) acc += __shfl_xor_sync(0xFFFFFFFFu, acc, o);
    __shared__ float red[8];
    if ((threadIdx.x & 31) == 0) red[threadIdx.x >> 5] = acc;
    __syncthreads();
    if (threadIdx.x == 0) {
        float tot = 0.f;
        #pragma unroll
        for (int w = 0; w < 8; w++) tot += red[w];
        atomicAdd(out, tot * (0.5f / ((float)NOBJ * (float)P)));
    }
}

// ---------------------------------------------------------------------------
extern "C" void kernel_launch(void* const* d_in, const int* in_sizes, int n_in,
                              void* d_out, int out_size)
{
    const float* set1 = (const float*)d_in[0];
    const float* set2 = (const float*)d_in[1];
    float* out = (float*)d_out;

    build_kernel<<<NSLOT, 256>>>(set1, set2, out);
    query_kernel<<<512, 256>>>(out);
}

// round 12
// speedup vs baseline: 4.0591x; 1.6255x over previous
#include <cuda_runtime.h>
#include <math.h>
#include <float.h>

#define NOBJ   16
#define P      4096
#define EPSF   1e-12f
#define GRID   64
#define NBINS  (GRID * GRID)          // 4096
#define NCHUNKS (NBINS / 256)         // 16
#define GMIN   (-5.0f)
#define GMAX   (5.0f)
#define GEXT   10.0f
#define CELLF  (GEXT / (float)GRID)   // 0.15625
#define CELL2  (CELLF * CELLF)
#define INVC   ((float)GRID / GEXT)   // 6.4
#define NSLOT  32                     // 2 sets x 16 objects
#define CSTRIDE (NBINS + 4)           // 16B-aligned slot stride
#define NQ     (2 * NOBJ * P)         // 131072 queries

// Sorted points and cell offsets per (set, object) slot.
__device__ __align__(16) float2       g_pts[NSLOT * P];
__device__ __align__(16) unsigned int g_cstart[NSLOT * CSTRIDE];
__device__ float        g_mask[NOBJ];

// Tail (phase-2) work list
__device__ unsigned int g_tail_count;
__device__ int          g_tail_qid [NQ];
__device__ float        g_tail_best[NQ];

__device__ __forceinline__ int cell_of(float v) {
    int c = (int)((v - GMIN) * INVC);
    return min(GRID - 1, max(0, c));
}

// ---------------------------------------------------------------------------
// Kernel 1: build — counting-sort each (set, obj) into the 64x64 grid.
// One CTA per slot. Also computes g_mask (set2), zeroes output + tail count.
// ---------------------------------------------------------------------------
__global__ void __launch_bounds__(256)
build_kernel(const float* __restrict__ set1, const float* __restrict__ set2,
             float* __restrict__ out)
{
    const int slot = blockIdx.x;
    const int set  = slot >> 4;
    const int obj  = slot & 15;
    const float2* pts = (const float2*)((set == 0 ? set1 : set2) + (size_t)obj * P * 2);

    __shared__ unsigned int hist[NBINS];     // 16 KB
    __shared__ unsigned int wsum[8];
    __shared__ unsigned int s_carry, s_total;

    const int tid = threadIdx.x;
    const int lane = tid & 31, warp = tid >> 5;

    for (int i = tid; i < NBINS; i += 256) hist[i] = 0;
    if (tid == 0) s_carry = 0;
    __syncthreads();

    float msum = 0.f;
    for (int i = tid; i < P; i += 256) {
        float2 p = pts[i];
        msum += p.x + p.y;
        int c = cell_of(p.y) * GRID + cell_of(p.x);
        atomicAdd(&hist[c], 1u);
    }

    if (set == 1) {
        #pragma unroll
        for (int o = 16; o; o >>= 1) msum += __shfl_xor_sync(0xFFFFFFFFu, msum, o);
        __shared__ float mred[8];
        if (lane == 0) mred[warp] = msum;
        __syncthreads();
        if (tid == 0) {
            float t = 0.f;
            #pragma unroll
            for (int w = 0; w < 8; w++) t += mred[w];
            g_mask[obj] = (t >= 0.f) ? 1.f : 0.f;
        }
    }
    if (slot == 0 && tid == 0) { *out = 0.f; g_tail_count = 0; }
    __syncthreads();

    // exclusive scan over NBINS (16 chunks of 256)
    for (int ch = 0; ch < NCHUNKS; ch++) {
        unsigned int v = hist[ch * 256 + tid];
        unsigned int incl = v;
        #pragma unroll
        for (int o = 1; o < 32; o <<= 1) {
            unsigned int n = __shfl_up_sync(0xFFFFFFFFu, incl, o);
            if (lane >= o) incl += n;
        }
        if (lane == 31) wsum[warp] = incl;
        __syncthreads();
        if (tid == 0) {
            unsigned int run = 0;
            #pragma unroll
            for (int w = 0; w < 8; w++) { unsigned int t = wsum[w]; wsum[w] = run; run += t; }
            s_total = run;
        }
        __syncthreads();
        hist[ch * 256 + tid] = (incl - v) + wsum[warp] + s_carry;
        __syncthreads();
        if (tid == 0) s_carry += s_total;
        __syncthreads();
    }

    unsigned int* cs = g_cstart + (size_t)slot * CSTRIDE;
    for (int i = tid; i < NBINS; i += 256) cs[i] = hist[i];
    if (tid == 0) { cs[NBINS] = P; cs[NBINS + 1] = P; cs[NBINS + 2] = P; cs[NBINS + 3] = P; }
    __syncthreads();

    float2* dst = g_pts + (size_t)slot * P;
    for (int i = tid; i < P; i += 256) {
        float2 p = pts[i];
        int c = cell_of(p.y) * GRID + cell_of(p.x);
        unsigned int pos = atomicAdd(&hist[c], 1u);
        dst[pos] = p;
    }
}

// ---------------------------------------------------------------------------
// Kernel 2 (phase 1): 3x3-only NN. If best <= CELL^2 the NN is proven found
// (unvisited cells are >= 1 cell away, using clamped-query geometry).
// Otherwise push (qid, best) to the tail list. Target structure in smem.
// ---------------------------------------------------------------------------
__global__ void __launch_bounds__(256)
query_kernel(float* __restrict__ out)
{
    const int b     = blockIdx.x;
    const int chunk = b & 15;
    const int obj   = (b >> 4) & 15;
    const int dir   = b >> 8;

    const int qslot = (dir == 0) ? obj      : 16 + obj;
    const int tslot = (dir == 0) ? 16 + obj : obj;

    __shared__ __align__(16) float2       s_pts[P];           // 32 KB
    __shared__ __align__(16) unsigned int s_cs[NBINS + 1];    // 16 KB

    {
        const float4* src = (const float4*)(g_pts + (size_t)tslot * P);
        float4* dst = (float4*)s_pts;
        for (int i = threadIdx.x; i < P / 2; i += 256) dst[i] = src[i];
        const uint4* csrc = (const uint4*)(g_cstart + (size_t)tslot * CSTRIDE);
        uint4* cdst = (uint4*)s_cs;
        for (int i = threadIdx.x; i < NBINS / 4; i += 256) cdst[i] = csrc[i];
        if (threadIdx.x == 0) s_cs[NBINS] = P;
    }
    __syncthreads();

    const int qi  = chunk * 256 + threadIdx.x;
    const int qid = (dir * NOBJ + obj) * P + qi;
    const float2 qp = g_pts[(size_t)qslot * P + qi];
    const float qx = qp.x, qy = qp.y;
    const int cx = cell_of(qx), cy = cell_of(qy);

    float best = FLT_MAX;
    {
        const int j0 = max(cy - 1, 0), j1 = min(cy + 1, GRID - 1);
        const int i0 = max(cx - 1, 0), i1 = min(cx + 1, GRID - 1);
        for (int j = j0; j <= j1; j++) {
            const unsigned int k0 = s_cs[j * GRID + i0];
            const unsigned int k1 = s_cs[j * GRID + i1 + 1];
            for (unsigned int k = k0; k < k1; k++) {
                const float2 p = s_pts[k];
                const float dx = qx - p.x;
                const float dy = qy - p.y;
                best = fminf(best, fmaf(dx, dx, dy * dy));
            }
        }
    }

    const bool fail = (best > CELL2);
    float acc = fail ? 0.f : sqrtf(fmaxf(best, EPSF)) * g_mask[obj];

    // warp-aggregated tail push
    const unsigned int m = __ballot_sync(0xFFFFFFFFu, fail);
    if (m) {
        const int lane = threadIdx.x & 31;
        const int leader = __ffs(m) - 1;
        unsigned int base = 0;
        if (lane == leader) base = atomicAdd(&g_tail_count, (unsigned)__popc(m));
        base = __shfl_sync(0xFFFFFFFFu, base, leader);
        if (fail) {
            const int off = base + __popc(m & ((1u << lane) - 1u));
            g_tail_qid[off]  = qid;
            g_tail_best[off] = best;
        }
    }

    // block reduce + atomic
    #pragma unroll
    for (int o = 16; o; o >>= 1) acc += __shfl_xor_sync(0xFFFFFFFFu, acc, o);
    __shared__ float red[8];
    if ((threadIdx.x & 31) == 0) red[threadIdx.x >> 5] = acc;
    __syncthreads();
    if (threadIdx.x == 0) {
        float tot = 0.f;
        #pragma unroll
        for (int w = 0; w < 8; w++) tot += red[w];
        if (tot != 0.f)
            atomicAdd(out, tot * (0.5f / ((float)NOBJ * (float)P)));
    }
}

// ---------------------------------------------------------------------------
// Kernel 3 (phase 2): tail queries, one WARP per query. Lanes split box rows;
// box radius doubles 2,4,...,64; exact stop best <= (r*CELL)^2 (clamped-query
// geometry). Row scan = contiguous span [x0..x1] in the sorted array.
// ---------------------------------------------------------------------------
__global__ void __launch_bounds__(128)
tail_kernel(float* __restrict__ out)
{
    const int warps_per_cta = 128 / 32;
    const int gwarp = blockIdx.x * warps_per_cta + (threadIdx.x >> 5);
    const int nwarp = gridDim.x * warps_per_cta;
    const int lane  = threadIdx.x & 31;

    const unsigned int count = g_tail_count;
    float acc = 0.f;

    for (unsigned int t = gwarp; t < count; t += nwarp) {
        const int qid = g_tail_qid[t];
        float best    = g_tail_best[t];
        const int dir = qid >> 16;              // qid = (dir*16+obj)*4096 + qi
        const int obj = (qid >> 12) & 15;
        const int qi  = qid & (P - 1);

        const int qslot = (dir == 0) ? obj      : 16 + obj;
        const int tslot = (dir == 0) ? 16 + obj : obj;

        const float2 qp = g_pts[(size_t)qslot * P + qi];
        const float qx = qp.x, qy = qp.y;
        const unsigned int* __restrict__ cs = g_cstart + (size_t)tslot * CSTRIDE;
        const float2* __restrict__ tp = g_pts + (size_t)tslot * P;

        const int cx = cell_of(qx), cy = cell_of(qy);

        for (int r = 2; r <= GRID; r <<= 1) {
            const int y0 = max(cy - r, 0), y1 = min(cy + r, GRID - 1);
            const int x0 = max(cx - r, 0), x1 = min(cx + r, GRID - 1);

            float lb = FLT_MAX;
            for (int j = y0 + lane; j <= y1; j += 32) {
                const unsigned int k0 = __ldg(&cs[j * GRID + x0]);
                const unsigned int k1 = __ldg(&cs[j * GRID + x1 + 1]);
                for (unsigned int k = k0; k < k1; k++) {
                    const float2 p = __ldg(&tp[k]);
                    const float dx = qx - p.x;
                    const float dy = qy - p.y;
                    lb = fminf(lb, fmaf(dx, dx, dy * dy));
                }
            }
            #pragma unroll
            for (int o = 16; o; o >>= 1)
                lb = fminf(lb, __shfl_xor_sync(0xFFFFFFFFu, lb, o));
            best = fminf(best, lb);

            const bool full = (x0 == 0) && (y0 == 0) && (x1 == GRID - 1) && (y1 == GRID - 1);
            const float rb = (float)r * CELLF;
            if (best <= rb * rb || full) break;
        }

        acc += sqrtf(fmaxf(best, EPSF)) * g_mask[obj];   // identical on all lanes
    }

    if (lane == 0 && acc != 0.f)
        atomicAdd(out, acc * (0.5f / ((float)NOBJ * (float)P)));
}

// ---------------------------------------------------------------------------
extern "C" void kernel_launch(void* const* d_in, const int* in_sizes, int n_in,
                              void* d_out, int out_size)
{
    const float* set1 = (const float*)d_in[0];
    const float* set2 = (const float*)d_in[1];
    float* out = (float*)d_out;

    build_kernel<<<NSLOT, 256>>>(set1, set2, out);
    query_kernel<<<512, 256>>>(out);
    tail_kernel<<<148, 128>>>(out);
}